// round 6
// baseline (speedup 1.0000x reference)
#include <cuda_runtime.h>

// Closed form: out[b][w] = prod_{j=0..w} cos(inputs[b][j]).
// (RZ diagonal -> no effect on <Z>; CNOT chain maps Z_w -> Z_0..Z_w;
//  product state factorizes; rz_params provably dead.)
//
// R6 floor probe: 2 rows per thread => 80B/thread, perfectly 16B-aligned,
// so all traffic is LDG.128/STG.128 (5 loads + 5 stores per thread vs
// 10+10 LDG.64/STG.64 across two threads in R5). 4096 threads =
// 64 CTAs x 64 threads, one wave. 20 independent MUFU.COS per thread
// (deep ILP); two independent 10-FMUL prefix chains.
// Prior rounds established the kernel is launch-ramp-bound (~4.5us
// harness floor); this is the last marginal term (LSU wavefronts).

#ifndef NWIRES
#define NWIRES 10
#endif
#define ROWS_PER_THREAD 2
#define FLOATS_PER_THREAD (NWIRES * ROWS_PER_THREAD)  // 20
#define VEC4_PER_THREAD (FLOATS_PER_THREAD / 4)       // 5
#define BLOCK_THREADS 64

__global__ void __launch_bounds__(BLOCK_THREADS)
quantum_prefix_cos_row2_kernel(const float* __restrict__ inputs,
                               float* __restrict__ out,
                               int nThreads)
{
    int t = blockIdx.x * BLOCK_THREADS + threadIdx.x;
    if (t >= nThreads) return;

    const float4* __restrict__ rin  = (const float4*)(inputs + t * FLOATS_PER_THREAD);
    float4*       __restrict__ rout = (float4*)(out + t * FLOATS_PER_THREAD);

    // 5 independent LDG.128 (MLP=5).
    float4 v[VEC4_PER_THREAD];
#pragma unroll
    for (int i = 0; i < VEC4_PER_THREAD; i++) v[i] = rin[i];

    // 20 independent hardware cosines.
    float c[FLOATS_PER_THREAD];
#pragma unroll
    for (int i = 0; i < VEC4_PER_THREAD; i++) {
        c[4 * i + 0] = __cosf(v[i].x);
        c[4 * i + 1] = __cosf(v[i].y);
        c[4 * i + 2] = __cosf(v[i].z);
        c[4 * i + 3] = __cosf(v[i].w);
    }

    // Two independent prefix-product chains (rows are 10 floats each).
    float o[FLOATS_PER_THREAD];
#pragma unroll
    for (int r = 0; r < ROWS_PER_THREAD; r++) {
        float acc = 1.0f;
#pragma unroll
        for (int j = 0; j < NWIRES; j++) {
            acc *= c[r * NWIRES + j];
            o[r * NWIRES + j] = acc;
        }
    }

    // 5 STG.128.
#pragma unroll
    for (int i = 0; i < VEC4_PER_THREAD; i++) {
        float4 s;
        s.x = o[4 * i + 0];
        s.y = o[4 * i + 1];
        s.z = o[4 * i + 2];
        s.w = o[4 * i + 3];
        rout[i] = s;
    }
}

extern "C" void kernel_launch(void* const* d_in, const int* in_sizes, int n_in,
                              void* d_out, int out_size)
{
    const float* inputs = (const float*)d_in[0];   // (B, 10) float32
    // d_in[1] = rz_params (10,) -- unused in the closed form.
    float* out = (float*)d_out;                    // (B, 10) float32

    int B = in_sizes[0] / NWIRES;                  // 8192
    int nThreads = B / ROWS_PER_THREAD;            // 4096
    int blocks = (nThreads + BLOCK_THREADS - 1) / BLOCK_THREADS;  // 64
    quantum_prefix_cos_row2_kernel<<<blocks, BLOCK_THREADS>>>(inputs, out, nThreads);
}

// round 7
// speedup vs baseline: 1.4276x; 1.4276x over previous
#include <cuda_runtime.h>

// Closed form: out[b][w] = prod_{j=0..w} cos(inputs[b][j]).
// (RZ diagonal -> no effect on <Z>; CNOT chain maps Z_w -> Z_0..Z_w;
//  product state factorizes; rz_params provably dead.)
//
// R7: R5's proven-minimal per-thread body (5 LDG.64 -> 10 independent
// MUFU.COS -> one 10-FMUL prefix chain -> 5 STG.64) with the launch
// reshaped from 128x64 to 256x32: all 148 SMs covered (R5 left 20
// idle), shorter per-SM critical path. R6 showed coverage matters;
// this maximizes it at zero instruction cost.

#ifndef NWIRES
#define NWIRES 10
#endif
#define BLOCK_THREADS 32
#define NPAIRS (NWIRES / 2)   // 5 float2 per row

__global__ void __launch_bounds__(BLOCK_THREADS)
quantum_prefix_cos_row_kernel(const float* __restrict__ inputs,
                              float* __restrict__ out,
                              int B)
{
    int b = blockIdx.x * BLOCK_THREADS + threadIdx.x;
    if (b >= B) return;

    const float2* __restrict__ rin  = (const float2*)(inputs + b * NWIRES);
    float2*       __restrict__ rout = (float2*)(out + b * NWIRES);

    // 5 independent LDG.64 (MLP=5). Rows are 40B = 8B-aligned.
    float2 v[NPAIRS];
#pragma unroll
    for (int i = 0; i < NPAIRS; i++) v[i] = rin[i];

    // 10 independent hardware cosines (RRO+MUFU, pipelined).
    float c[NWIRES];
#pragma unroll
    for (int i = 0; i < NPAIRS; i++) {
        c[2 * i]     = __cosf(v[i].x);
        c[2 * i + 1] = __cosf(v[i].y);
    }

    // Serial prefix product (the only dependent chain, 10 FMUL).
    float acc = c[0];
    float2 o[NPAIRS];
    o[0].x = acc;
#pragma unroll
    for (int j = 1; j < NWIRES; j++) {
        acc *= c[j];
        if (j & 1) o[j >> 1].y = acc;
        else       o[j >> 1].x = acc;
    }

#pragma unroll
    for (int i = 0; i < NPAIRS; i++) rout[i] = o[i];
}

extern "C" void kernel_launch(void* const* d_in, const int* in_sizes, int n_in,
                              void* d_out, int out_size)
{
    const float* inputs = (const float*)d_in[0];   // (B, 10) float32
    // d_in[1] = rz_params (10,) -- unused in the closed form.
    float* out = (float*)d_out;                    // (B, 10) float32

    int B = in_sizes[0] / NWIRES;                  // 8192
    int blocks = (B + BLOCK_THREADS - 1) / BLOCK_THREADS;  // 256
    quantum_prefix_cos_row_kernel<<<blocks, BLOCK_THREADS>>>(inputs, out, B);
}